// round 16
// baseline (speedup 1.0000x reference)
#include <cuda_runtime.h>
#include <cuda_fp16.h>
#include <math.h>
#include <stdint.h>
#include <string.h>

#define D_MODEL 1024
#define NHEAD 16
#define HEAD_DIM 64
#define B_ 2
#define L_ 2048
#define M_TOK 4096
#define D_FF 4096
#define QKVS 3072
#define OUT_MAIN (M_TOK * D_MODEL)

// ---------------- scratch (device globals; no allocations allowed) ----------
__device__ float g_x[M_TOK * D_MODEL];
__device__ float g_y[M_TOK * D_MODEL];
__device__ float g_qbias[M_TOK * NHEAD];
__device__ float g_kbias[M_TOK * NHEAD];
__device__ float g_bqkv[QKVS];
__device__ float g_entpart[1024];
__device__ __half g_src_f[M_TOK * D_MODEL];
__device__ __half g_qkv[M_TOK * QKVS];
__device__ __half g_at_f[M_TOK * D_MODEL];
__device__ __half g_x_f[M_TOK * D_MODEL];
__device__ __half g_ff_f[M_TOK * D_FF];
__device__ __half g_w4[4 * D_MODEL * D_MODEL];
__device__ __half g_w1[D_FF * D_MODEL];
__device__ __half g_w2[D_MODEL * D_FF];

// ======================= PTX helpers (baseline sm_103-legal only) ===========
__device__ __forceinline__ uint32_t smem_u32(const void* p) {
    uint32_t a;
    asm("{ .reg .u64 t; cvta.to.shared.u64 t, %1; cvt.u32.u64 %0, t; }" : "=r"(a) : "l"(p));
    return a;
}
__device__ __forceinline__ void cp16(uint32_t s, const void* g) {
    asm volatile("cp.async.cg.shared.global [%0], [%1], 16;" :: "r"(s), "l"(g));
}
__device__ __forceinline__ void cp4(uint32_t s, const void* g) {
    asm volatile("cp.async.ca.shared.global [%0], [%1], 4;" :: "r"(s), "l"(g));
}
#define CP_COMMIT() asm volatile("cp.async.commit_group;" ::: "memory")

__device__ __forceinline__ void ldsm4(uint32_t* r, uint32_t addr) {
    asm volatile("ldmatrix.sync.aligned.m8n8.x4.shared.b16 {%0,%1,%2,%3}, [%4];"
                 : "=r"(r[0]), "=r"(r[1]), "=r"(r[2]), "=r"(r[3]) : "r"(addr));
}
__device__ __forceinline__ void ldsm4t(uint32_t* r, uint32_t addr) {
    asm volatile("ldmatrix.sync.aligned.m8n8.x4.trans.shared.b16 {%0,%1,%2,%3}, [%4];"
                 : "=r"(r[0]), "=r"(r[1]), "=r"(r[2]), "=r"(r[3]) : "r"(addr));
}
__device__ __forceinline__ void mma16816(float* d, const uint32_t* a, uint32_t b0, uint32_t b1) {
    asm volatile(
        "mma.sync.aligned.m16n8k16.row.col.f32.f16.f16.f32 "
        "{%0,%1,%2,%3}, {%4,%5,%6,%7}, {%8,%9}, {%0,%1,%2,%3};"
        : "+f"(d[0]), "+f"(d[1]), "+f"(d[2]), "+f"(d[3])
        : "r"(a[0]), "r"(a[1]), "r"(a[2]), "r"(a[3]), "r"(b0), "r"(b1));
}
__device__ __forceinline__ uint32_t packh(float a, float b) {
    __half2 t = __floats2half2_rn(a, b);
    uint32_t u; memcpy(&u, &t, 4); return u;
}

// ======================= warp-MMA fp16 GEMM =================================
// 128x64 CTA tile, BKC=64, SW128 swizzle, 3 stages, 1 sync/chunk, 3 CTAs/SM.
// MODE 0: fp32 +bias  MODE 1: gelu(+bias)->fp16  MODE 2: fp32 +bias+res
// MODE 3: +bias -> fp16
#define BM 128
#define BN 64
#define BKC 64
#define TILE_A (128 * 128)               // 16384
#define TILE_W (64 * 128)                // 8192
#define STAGE_B (TILE_A + TILE_W)        // 24576
#define NSTAGE 3
#define GEMM_SMEM (NSTAGE * STAGE_B)     // 73728 -> 3 CTAs/SM

__device__ __forceinline__ void g_load_chunk(
    uint32_t smem, int ci, int m0, int n0, int K, int tid,
    const __half* __restrict__ A, const __half* __restrict__ W)
{
    uint32_t sb = smem + (uint32_t)(ci % NSTAGE) * STAGE_B;
    size_t kbase = (size_t)ci * BKC;
#pragma unroll
    for (int rep = 0; rep < 6; rep++) {
        int idx = tid + (rep << 8);          // 0..1535
        int isB = idx >> 10;                 // 0 = A (1024), 1 = W (512)
        int row = (idx >> 3) & (isB ? 63 : 127);
        int seg = idx & 7;
        const __half* P = isB ? W : A;
        int r0 = isB ? n0 : m0;
        uint32_t off = isB ? (uint32_t)TILE_A : 0u;
        uint32_t sw = (uint32_t)((seg << 4) ^ ((row & 7) << 4));
        cp16(sb + off + (uint32_t)(row << 7) + sw,
             P + (size_t)(r0 + row) * K + kbase + seg * 8);
    }
}

template <int MODE>
__global__ void __launch_bounds__(256, 3) tcgemm_kernel(
    const __half* __restrict__ A, const __half* __restrict__ W,
    const float* __restrict__ bias, const float* __restrict__ res,
    float* __restrict__ C, __half* __restrict__ Cf,
    int M, int N, int K)
{
    extern __shared__ char dsm[];
    uint32_t smem = smem_u32(dsm);

    int tid = threadIdx.x;
    int wid = tid >> 5;
    int lane = tid & 31;
    int m0 = blockIdx.y * BM;
    int n0 = blockIdx.x * BN;
    int nchunk = K / BKC;

    int wm = wid & 3;          // 4 M-groups of 32
    int wn = wid >> 2;         // 2 N-groups of 32
    int lr = lane & 15;
    uint32_t lk = (uint32_t)((lane >> 4) << 4);
    uint32_t swz = (uint32_t)((lr & 7) << 4);

    float acc[2][4][4];
#pragma unroll
    for (int i = 0; i < 2; i++)
#pragma unroll
        for (int j = 0; j < 4; j++)
#pragma unroll
            for (int c = 0; c < 4; c++) acc[i][j][c] = 0.0f;

    g_load_chunk(smem, 0, m0, n0, K, tid, A, W);
    CP_COMMIT();
    g_load_chunk(smem, 1, m0, n0, K, tid, A, W);
    CP_COMMIT();

    for (int i = 0; i < nchunk; i++) {
        if (i < nchunk - 1)
            asm volatile("cp.async.wait_group 1;" ::: "memory");
        else
            asm volatile("cp.async.wait_group 0;" ::: "memory");
        __syncthreads();

        if (i + 2 < nchunk) {
            g_load_chunk(smem, i + 2, m0, n0, K, tid, A, W);
            CP_COMMIT();
        }

        uint32_t sb = smem + (uint32_t)(i % NSTAGE) * STAGE_B;
        uint32_t aRow = sb + (uint32_t)((wm * 32 + lr) << 7);
        uint32_t bRow = sb + TILE_A + (uint32_t)((wn * 32 + lr) << 7);

#pragma unroll
        for (int ks = 0; ks < 4; ks++) {
            uint32_t col = ((uint32_t)(ks * 32) + lk) ^ swz;
            uint32_t ah[2][4], bb[2][4];
            ldsm4(ah[0], aRow + col);
            ldsm4(ah[1], aRow + (1u << 11) + col);
            ldsm4(bb[0], bRow + col);
            ldsm4(bb[1], bRow + (1u << 11) + col);
#pragma unroll
            for (int nt = 0; nt < 2; nt++)
#pragma unroll
                for (int mt = 0; mt < 2; mt++) {
                    mma16816(acc[mt][nt * 2],     ah[mt], bb[nt][0], bb[nt][2]);
                    mma16816(acc[mt][nt * 2 + 1], ah[mt], bb[nt][1], bb[nt][3]);
                }
        }
    }

    int rbase = m0 + wm * 32 + (lane >> 2);
    int cbase = n0 + wn * 32 + (lane & 3) * 2;
#pragma unroll
    for (int mt = 0; mt < 2; mt++) {
#pragma unroll
        for (int n8 = 0; n8 < 4; n8++) {
            int col = cbase + n8 * 8;
            float b0 = bias[col], b1 = bias[col + 1];
#pragma unroll
            for (int half = 0; half < 2; half++) {
                int row = rbase + mt * 16 + half * 8;
                float v0 = acc[mt][n8][half * 2] + b0;
                float v1 = acc[mt][n8][half * 2 + 1] + b1;
                if (MODE == 1) {
                    v0 = 0.5f * v0 * (1.0f + erff(v0 * 0.70710678118654752f));
                    v1 = 0.5f * v1 * (1.0f + erff(v1 * 0.70710678118654752f));
                }
                if (MODE == 2) {
                    const float2 rv = *(const float2*)(res + (size_t)row * N + col);
                    v0 += rv.x; v1 += rv.y;
                }
                if (MODE == 0 || MODE == 2) {
                    float2 o; o.x = v0; o.y = v1;
                    *(float2*)(C + (size_t)row * N + col) = o;
                } else {
                    *(__half2*)(Cf + (size_t)row * N + col) = __floats2half2_rn(v0, v1);
                }
            }
        }
    }
}

// ======================= MMA flash attention (unchanged) ====================
#define ASTR 144
#define ATILE (64 * ASTR)
#define ASTAGE (2 * ATILE + 256)
#define ANST 3
#define ASMEM (ANST * ASTAGE + 64)

__device__ __forceinline__ void a_load_chunk(
    uint32_t sm0, int ci, size_t tokb, int h, int tid,
    const __half* __restrict__ QKV, const float* __restrict__ kb)
{
    uint32_t st = sm0 + (uint32_t)(ci % ANST) * ASTAGE;
    size_t rowb = tokb + (size_t)ci * 64;
#pragma unroll
    for (int r = 0; r < 4; r++) {
        int idx = tid + (r << 8);
        int t = idx >> 9;
        int row = (idx >> 3) & 63;
        int seg = idx & 7;
        cp16(st + (uint32_t)t * ATILE + (uint32_t)row * ASTR + (uint32_t)seg * 16,
             QKV + (rowb + row) * QKVS + (t + 1) * D_MODEL + h * HEAD_DIM + seg * 8);
    }
    if (tid < 64)
        cp4(st + 2u * ATILE + (uint32_t)tid * 4, kb + (rowb + tid) * NHEAD + h);
}

__global__ void __launch_bounds__(256, 2) attn_mma_kernel(
    const __half* __restrict__ QKV,
    const float* __restrict__ qb, const float* __restrict__ kb,
    const float* __restrict__ temp,
    __half* __restrict__ Of, float* __restrict__ ent_part)
{
    extern __shared__ char smemv[];
    uint32_t sm0 = smem_u32(smemv);
    float* red = (float*)(smemv + ANST * ASTAGE);

    int tid = threadIdx.x;
    int w = tid >> 5;
    int lane = tid & 31;
    int q0 = blockIdx.x * 128;
    int h = blockIdx.y;
    int b = blockIdx.z;
    size_t tokb = (size_t)b * L_;

    float tmph = fminf(fmaxf(temp[h], 0.1f), 5.0f);
    float inv_t = 1.0f / tmph;
    float sc = 0.125f * inv_t;

    uint32_t qarea = sm0 + 2u * ASTAGE;
    for (int i = tid; i < 128 * 8; i += 256) {
        int row = i >> 3, seg = i & 7;
        cp16(qarea + (uint32_t)row * ASTR + (uint32_t)seg * 16,
             QKV + (tokb + q0 + row) * QKVS + h * HEAD_DIM + seg * 8);
    }
    CP_COMMIT();
    a_load_chunk(sm0, 0, tokb, h, tid, QKV, kb);
    CP_COMMIT();
    a_load_chunk(sm0, 1, tokb, h, tid, QKV, kb);
    CP_COMMIT();

    asm volatile("cp.async.wait_group 2;" ::: "memory");
    __syncthreads();

    uint32_t qfr[4][4];
    {
        uint32_t qbase = qarea + (uint32_t)(w * 16 + (lane & 15)) * ASTR + (uint32_t)((lane >> 4) << 4);
#pragma unroll
        for (int ks = 0; ks < 4; ks++) ldsm4(qfr[ks], qbase + ks * 32);
    }
    int gid = lane >> 2, tig = lane & 3;
    int r0 = q0 + w * 16 + gid, r1 = r0 + 8;
    float qb0 = qb[(tokb + r0) * NHEAD + h] * inv_t;
    float qb1 = qb[(tokb + r1) * NHEAD + h] * inv_t;

    float O[8][4];
#pragma unroll
    for (int f = 0; f < 8; f++)
#pragma unroll
        for (int c = 0; c < 4; c++) O[f][c] = 0.0f;
    float m0 = -1e30f, m1 = -1e30f, z0 = 0.0f, z1 = 0.0f, t0 = 0.0f, t1 = 0.0f;

    const int NCH = L_ / 64;
    for (int ci = 0; ci < NCH; ci++) {
        if (ci < NCH - 1)
            asm volatile("cp.async.wait_group 1;" ::: "memory");
        else
            asm volatile("cp.async.wait_group 0;" ::: "memory");
        __syncthreads();

        if (ci + 2 < NCH) {
            a_load_chunk(sm0, ci + 2, tokb, h, tid, QKV, kb);
            CP_COMMIT();
        }

        uint32_t st = sm0 + (uint32_t)(ci % ANST) * ASTAGE;
        uint32_t kbh = st + (uint32_t)(lane & 15) * ASTR + (uint32_t)((lane >> 4) << 4);

        float S[8][4];
#pragma unroll
        for (int f = 0; f < 8; f++)
#pragma unroll
            for (int c = 0; c < 4; c++) S[f][c] = 0.0f;

#pragma unroll
        for (int ks = 0; ks < 4; ks++) {
            uint32_t koff = (uint32_t)ks * 32;
#pragma unroll
            for (int nt = 0; nt < 4; nt++) {
                uint32_t bb[4];
                ldsm4(bb, kbh + (uint32_t)(nt * 16) * ASTR + koff);
                mma16816(S[nt * 2],     qfr[ks], bb[0], bb[2]);
                mma16816(S[nt * 2 + 1], qfr[ks], bb[1], bb[3]);
            }
        }

        const float* kbs = (const float*)(smemv + (size_t)((ci % ANST) * ASTAGE + 2 * ATILE));
        float mx0 = -1e30f, mx1 = -1e30f;
#pragma unroll
        for (int f = 0; f < 8; f++) {
            float kc0 = kbs[f * 8 + 2 * tig] * inv_t;
            float kc1 = kbs[f * 8 + 2 * tig + 1] * inv_t;
            S[f][0] = S[f][0] * sc + qb0 + kc0;
            S[f][1] = S[f][1] * sc + qb0 + kc1;
            S[f][2] = S[f][2] * sc + qb1 + kc0;
            S[f][3] = S[f][3] * sc + qb1 + kc1;
            mx0 = fmaxf(mx0, fmaxf(S[f][0], S[f][1]));
            mx1 = fmaxf(mx1, fmaxf(S[f][2], S[f][3]));
        }
        mx0 = fmaxf(mx0, __shfl_xor_sync(0xffffffffu, mx0, 1));
        mx0 = fmaxf(mx0, __shfl_xor_sync(0xffffffffu, mx0, 2));
        mx1 = fmaxf(mx1, __shfl_xor_sync(0xffffffffu, mx1, 1));
        mx1 = fmaxf(mx1, __shfl_xor_sync(0xffffffffu, mx1, 2));

        float nm0 = fmaxf(m0, mx0), nm1 = fmaxf(m1, mx1);
        float sc0 = __expf(m0 - nm0), sc1 = __expf(m1 - nm1);
        float zc0 = 0.0f, zc1 = 0.0f, tc0 = 0.0f, tc1 = 0.0f;
        uint32_t pa[4][4];
#pragma unroll
        for (int j = 0; j < 4; j++) {
#pragma unroll
            for (int g = 0; g < 2; g++) {
                int f = 2 * j + g;
                float p0 = __expf(S[f][0] - nm0);
                float p1 = __expf(S[f][1] - nm0);
                float p2 = __expf(S[f][2] - nm1);
                float p3 = __expf(S[f][3] - nm1);
                zc0 += p0 + p1; zc1 += p2 + p3;
                tc0 += p0 * S[f][0] + p1 * S[f][1];
                tc1 += p2 * S[f][2] + p3 * S[f][3];
                pa[j][g * 2]     = packh(p0, p1);
                pa[j][g * 2 + 1] = packh(p2, p3);
            }
        }
        zc0 += __shfl_xor_sync(0xffffffffu, zc0, 1); zc0 += __shfl_xor_sync(0xffffffffu, zc0, 2);
        zc1 += __shfl_xor_sync(0xffffffffu, zc1, 1); zc1 += __shfl_xor_sync(0xffffffffu, zc1, 2);
        tc0 += __shfl_xor_sync(0xffffffffu, tc0, 1); tc0 += __shfl_xor_sync(0xffffffffu, tc0, 2);
        tc1 += __shfl_xor_sync(0xffffffffu, tc1, 1); tc1 += __shfl_xor_sync(0xffffffffu, tc1, 2);
        z0 = z0 * sc0 + zc0; t0 = t0 * sc0 + tc0; m0 = nm0;
        z1 = z1 * sc1 + zc1; t1 = t1 * sc1 + tc1; m1 = nm1;
#pragma unroll
        for (int f = 0; f < 8; f++) {
            O[f][0] *= sc0; O[f][1] *= sc0; O[f][2] *= sc1; O[f][3] *= sc1;
        }

        uint32_t vb = st + ATILE + (uint32_t)(lane & 15) * ASTR + (uint32_t)((lane >> 4) << 4);
#pragma unroll
        for (int j = 0; j < 4; j++) {
            uint32_t vrow = vb + (uint32_t)(j * 16) * ASTR;
#pragma unroll
            for (int hg = 0; hg < 4; hg++) {
                uint32_t v[4];
                ldsm4t(v, vrow + (uint32_t)hg * 32);
                mma16816(O[hg * 2],     pa[j], v[0], v[1]);
                mma16816(O[hg * 2 + 1], pa[j], v[2], v[3]);
            }
        }
    }

    float iz0 = 1.0f / z0, iz1 = 1.0f / z1;
    size_t row0b = (tokb + r0) * D_MODEL, row1b = (tokb + r1) * D_MODEL;
#pragma unroll
    for (int f = 0; f < 8; f++) {
        int col = h * HEAD_DIM + f * 8 + 2 * tig;
        *(__half2*)(Of + row0b + col) = __floats2half2_rn(O[f][0] * iz0, O[f][1] * iz0);
        *(__half2*)(Of + row1b + col) = __floats2half2_rn(O[f][2] * iz1, O[f][3] * iz1);
    }

    float Hv = (m0 + logf(z0) - t0 / z0 + m1 + logf(z1) - t1 / z1) * 0.25f;
#pragma unroll
    for (int off = 16; off; off >>= 1) Hv += __shfl_xor_sync(0xffffffffu, Hv, off);
    if (lane == 0) red[w] = Hv;
    __syncthreads();
    if (tid == 0) {
        float s = 0.0f;
#pragma unroll
        for (int i = 0; i < 8; i++) s += red[i];
        ent_part[((b * NHEAD + h) << 4) + blockIdx.x] = s;
    }
}

// ======================= all weight transposes in ONE launch ================
__global__ void __launch_bounds__(256) convAll_kernel(
    const float* __restrict__ Wq, const float* __restrict__ Wk,
    const float* __restrict__ Wv, const float* __restrict__ Wo,
    const float* __restrict__ W1, const float* __restrict__ W2,
    __half* __restrict__ w4, __half* __restrict__ w1o, __half* __restrict__ w2o)
{
    __shared__ float t[32][33];
    int id = blockIdx.x;
    const float* W; __half* dst; int K, N, n0, k0;
    if (id < 4096) {
        int slab = id >> 10, tt = id & 1023;
        W = (slab == 0) ? Wq : (slab == 1) ? Wk : (slab == 2) ? Wv : Wo;
        dst = w4 + (size_t)slab * D_MODEL * D_MODEL;
        K = D_MODEL; N = D_MODEL;
        n0 = (tt & 31) << 5; k0 = (tt >> 5) << 5;
    } else if (id < 8192) {
        int tt = id - 4096;
        W = W1; dst = w1o; K = D_MODEL; N = D_FF;
        n0 = (tt & 127) << 5; k0 = (tt >> 7) << 5;
    } else {
        int tt = id - 8192;
        W = W2; dst = w2o; K = D_FF; N = D_MODEL;
        n0 = (tt & 31) << 5; k0 = (tt >> 5) << 5;
    }
    int tx = threadIdx.x & 31, ty = threadIdx.x >> 5;
#pragma unroll
    for (int i = 0; i < 32; i += 8)
        t[ty + i][tx] = W[(size_t)(k0 + ty + i) * N + n0 + tx];
    __syncthreads();
#pragma unroll
    for (int i = 0; i < 32; i += 8)
        dst[(size_t)(n0 + ty + i) * K + k0 + tx] = __float2half_rn(t[tx][ty + i]);
}

__global__ void __launch_bounds__(256) conv_kernel(
    const float* __restrict__ in, __half* __restrict__ outp, int n4,
    const float* __restrict__ bq, const float* __restrict__ bk,
    const float* __restrict__ bv, float* __restrict__ bqkv)
{
    if (blockIdx.x == gridDim.x - 1) {
        int tid = threadIdx.x;
        for (int i = tid; i < D_MODEL; i += 256) {
            bqkv[i] = bq[i];
            bqkv[i + D_MODEL] = bk[i];
            bqkv[i + 2 * D_MODEL] = bv[i];
        }
        return;
    }
    int i = blockIdx.x * 256 + threadIdx.x;
    if (i >= n4) return;
    float4 v = ((const float4*)in)[i];
    ((__half2*)outp)[i * 2]     = __floats2half2_rn(v.x, v.y);
    ((__half2*)outp)[i * 2 + 1] = __floats2half2_rn(v.z, v.w);
}

// ---------------- POS bias MLPs ----------------------------------------------
__global__ void __launch_bounds__(128) posbias_kernel(
    const float* __restrict__ pos,
    const float* __restrict__ qw1, const float* __restrict__ qb1,
    const float* __restrict__ qw2, const float* __restrict__ qb2,
    const float* __restrict__ kw1, const float* __restrict__ kb1,
    const float* __restrict__ kw2, const float* __restrict__ kb2,
    float* __restrict__ qbias, float* __restrict__ kbias)
{
    __shared__ float sw1q[32 * 32], sw2q[32 * 16], sb1q[32], sb2q[16];
    __shared__ float sw1k[32 * 32], sw2k[32 * 16], sb1k[32], sb2k[16];
    int tid = threadIdx.x;
    for (int i = tid; i < 1024; i += 128) { sw1q[i] = qw1[i]; sw1k[i] = kw1[i]; }
    for (int i = tid; i < 512;  i += 128) { sw2q[i] = qw2[i]; sw2k[i] = kw2[i]; }
    if (tid < 32) { sb1q[tid] = qb1[tid]; sb1k[tid] = kb1[tid]; }
    if (tid < 16) { sb2q[tid] = qb2[tid]; sb2k[tid] = kb2[tid]; }
    __syncthreads();

    int token = blockIdx.x * 128 + tid;
    float pf[32];
#pragma unroll
    for (int i = 0; i < 32; i++) pf[i] = pos[(size_t)token * 32 + i];

    float hq[32], hk[32];
#pragma unroll
    for (int j = 0; j < 32; j++) { hq[j] = sb1q[j]; hk[j] = sb1k[j]; }
    for (int i = 0; i < 32; i++) {
        float p = pf[i];
#pragma unroll
        for (int j = 0; j < 32; j++) {
            hq[j] += p * sw1q[i * 32 + j];
            hk[j] += p * sw1k[i * 32 + j];
        }
    }
#pragma unroll
    for (int j = 0; j < 32; j++) {
        hq[j] = fmaxf(hq[j], 0.0f);
        hk[j] = fmaxf(hk[j], 0.0f);
    }
#pragma unroll
    for (int h = 0; h < 16; h++) {
        float oq = sb2q[h], ok = sb2k[h];
        for (int j = 0; j < 32; j++) {
            oq += hq[j] * sw2q[j * 16 + h];
            ok += hk[j] * sw2k[j * 16 + h];
        }
        qbias[(size_t)token * NHEAD + h] = oq;
        kbias[(size_t)token * NHEAD + h] = ok;
    }
}

// ---------------- layernorm (optionally emits fp16) --------------------------
template <int SPLIT>
__global__ void __launch_bounds__(256) ln_kernel(
    const float* __restrict__ in, const float* __restrict__ gam,
    const float* __restrict__ bet, float* __restrict__ out,
    __half* __restrict__ of)
{
    int row = blockIdx.x, tid = threadIdx.x;
    float4 v = ((const float4*)(in + (size_t)row * D_MODEL))[tid];
    float s = v.x + v.y + v.z + v.w;
    float q = v.x * v.x + v.y * v.y + v.z * v.z + v.w * v.w;
#pragma unroll
    for (int off = 16; off; off >>= 1) {
        s += __shfl_xor_sync(0xffffffffu, s, off);
        q += __shfl_xor_sync(0xffffffffu, q, off);
    }
    __shared__ float ws[8], wq[8], stats[2];
    int lane = tid & 31, w = tid >> 5;
    if (lane == 0) { ws[w] = s; wq[w] = q; }
    __syncthreads();
    if (tid == 0) {
        float S = 0.0f, Qq = 0.0f;
        for (int i = 0; i < 8; i++) { S += ws[i]; Qq += wq[i]; }
        float mu  = S * (1.0f / D_MODEL);
        float var = Qq * (1.0f / D_MODEL) - mu * mu;
        stats[0] = mu;
        stats[1] = rsqrtf(var + 1e-5f);
    }
    __syncthreads();
    float mu = stats[0], rs = stats[1];
    float4 gv = ((const float4*)gam)[tid];
    float4 bv = ((const float4*)bet)[tid];
    float4 ov;
    ov.x = (v.x - mu) * rs * gv.x + bv.x;
    ov.y = (v.y - mu) * rs * gv.y + bv.y;
    ov.z = (v.z - mu) * rs * gv.z + bv.z;
    ov.w = (v.w - mu) * rs * gv.w + bv.w;
    ((float4*)(out + (size_t)row * D_MODEL))[tid] = ov;
    if (SPLIT) {
        size_t base = (size_t)row * D_MODEL + tid * 4;
        *(__half2*)(of + base)     = __floats2half2_rn(ov.x, ov.y);
        *(__half2*)(of + base + 2) = __floats2half2_rn(ov.z, ov.w);
    }
}

// ---------------- deterministic entropy reduction ----------------------------
__global__ void __launch_bounds__(256) ent_final_kernel(
    const float* __restrict__ part, float* __restrict__ out, int out_size)
{
    __shared__ float sm[256];
    int tid = threadIdx.x;
    sm[tid] = part[tid] + part[tid + 256];
    __syncthreads();
    for (int off = 128; off; off >>= 1) {
        if (tid < off) sm[tid] += sm[tid + off];
        __syncthreads();
    }
    if (tid == 0 && out_size > OUT_MAIN)
        out[OUT_MAIN] = sm[0] * (1.0f / (B_ * NHEAD * L_));
}

// ---------------- launch -----------------------------------------------------
extern "C" void kernel_launch(void* const* d_in, const int* in_sizes, int n_in,
                              void* d_out, int out_size)
{
    const float* src   = (const float*)d_in[0];
    const float* pos   = (const float*)d_in[1];
    const float* Wq    = (const float*)d_in[2];
    const float* bq    = (const float*)d_in[3];
    const float* Wk    = (const float*)d_in[4];
    const float* bk    = (const float*)d_in[5];
    const float* Wv    = (const float*)d_in[6];
    const float* bv    = (const float*)d_in[7];
    const float* Wo    = (const float*)d_in[8];
    const float* bo    = (const float*)d_in[9];
    const float* pq_w1 = (const float*)d_in[10];
    const float* pq_b1 = (const float*)d_in[11];
    const float* pq_w2 = (const float*)d_in[12];
    const float* pq_b2 = (const float*)d_in[13];
    const float* pk_w1 = (const float*)d_in[14];
    const float* pk_b1 = (const float*)d_in[15];
    const float* pk_w2 = (const float*)d_in[16];
    const float* pk_b2 = (const float*)d_in[17];
    const float* temp  = (const float*)d_in[18];
    const float* ln1g  = (const float*)d_in[19];
    const float* ln1b  = (const float*)d_in[20];
    const float* ln2g  = (const float*)d_in[21];
    const float* ln2b  = (const float*)d_in[22];
    const float* W1    = (const float*)d_in[23];
    const float* b1    = (const float*)d_in[24];
    const float* W2    = (const float*)d_in[25];
    const float* b2    = (const float*)d_in[26];
    float* out = (float*)d_out;

    float *xb, *yb, *qbb, *kbb, *entp, *bqkv;
    cudaGetSymbolAddress((void**)&xb, g_x);
    cudaGetSymbolAddress((void**)&yb, g_y);
    cudaGetSymbolAddress((void**)&qbb, g_qbias);
    cudaGetSymbolAddress((void**)&kbb, g_kbias);
    cudaGetSymbolAddress((void**)&entp, g_entpart);
    cudaGetSymbolAddress((void**)&bqkv, g_bqkv);

    __half *srcf, *qkv, *atf, *xf, *fff;
    __half *w4, *w116, *w216;
    cudaGetSymbolAddress((void**)&srcf, g_src_f);
    cudaGetSymbolAddress((void**)&qkv, g_qkv);
    cudaGetSymbolAddress((void**)&atf, g_at_f);
    cudaGetSymbolAddress((void**)&xf, g_x_f);
    cudaGetSymbolAddress((void**)&fff, g_ff_f);
    cudaGetSymbolAddress((void**)&w4, g_w4);
    cudaGetSymbolAddress((void**)&w116, g_w1);
    cudaGetSymbolAddress((void**)&w216, g_w2);

    __half* wo16 = w4 + 3 * (size_t)D_MODEL * D_MODEL;

    cudaFuncSetAttribute(tcgemm_kernel<1>, cudaFuncAttributeMaxDynamicSharedMemorySize, GEMM_SMEM);
    cudaFuncSetAttribute(tcgemm_kernel<2>, cudaFuncAttributeMaxDynamicSharedMemorySize, GEMM_SMEM);
    cudaFuncSetAttribute(tcgemm_kernel<3>, cudaFuncAttributeMaxDynamicSharedMemorySize, GEMM_SMEM);
    cudaFuncSetAttribute(attn_mma_kernel, cudaFuncAttributeMaxDynamicSharedMemorySize, ASMEM);

    convAll_kernel<<<12288, 256>>>(Wq, Wk, Wv, Wo, W1, W2, w4, w116, w216);
    conv_kernel<<<M_TOK * D_MODEL / 4 / 256 + 1, 256>>>(src, srcf, M_TOK * D_MODEL / 4,
                                                        bq, bk, bv, bqkv);
    posbias_kernel<<<M_TOK / 128, 128>>>(pos, pq_w1, pq_b1, pq_w2, pq_b2,
                                         pk_w1, pk_b1, pk_w2, pk_b2, qbb, kbb);

    dim3 gQKV(QKVS / BN, M_TOK / BM);   // (48, 32)
    tcgemm_kernel<3><<<gQKV, 256, GEMM_SMEM>>>(srcf, w4, bqkv, (const float*)0,
                                               (float*)0, qkv, M_TOK, QKVS, D_MODEL);

    attn_mma_kernel<<<dim3(L_ / 128, NHEAD, B_), 256, ASMEM>>>(
        qkv, qbb, kbb, temp, atf, entp);

    dim3 gD(D_MODEL / BN, M_TOK / BM);  // (16, 32)
    tcgemm_kernel<2><<<gD, 256, GEMM_SMEM>>>(atf, wo16, bo, src,
                                             yb, (__half*)0, M_TOK, D_MODEL, D_MODEL);
    ln_kernel<1><<<M_TOK, 256>>>(yb, ln1g, ln1b, xb, xf);

    dim3 gF(D_FF / BN, M_TOK / BM);     // (64, 32)
    tcgemm_kernel<1><<<gF, 256, GEMM_SMEM>>>(xf, w116, b1, (const float*)0,
                                             (float*)0, fff, M_TOK, D_FF, D_MODEL);
    tcgemm_kernel<2><<<gD, 256, GEMM_SMEM>>>(fff, w216, b2, xb,
                                             yb, (__half*)0, M_TOK, D_MODEL, D_FF);
    ln_kernel<0><<<M_TOK, 256>>>(yb, ln2g, ln2b, out, (__half*)0);

    ent_final_kernel<<<1, 256>>>(entp, out, out_size);
}

// round 17
// speedup vs baseline: 1.0250x; 1.0250x over previous
#include <cuda_runtime.h>
#include <cuda_fp16.h>
#include <math.h>
#include <stdint.h>
#include <string.h>

#define D_MODEL 1024
#define NHEAD 16
#define HEAD_DIM 64
#define B_ 2
#define L_ 2048
#define M_TOK 4096
#define D_FF 4096
#define QKVS 3072
#define OUT_MAIN (M_TOK * D_MODEL)

// ---------------- scratch (device globals; no allocations allowed) ----------
__device__ float g_x[M_TOK * D_MODEL];
__device__ float g_y[M_TOK * D_MODEL];
__device__ float g_qbias[M_TOK * NHEAD];
__device__ float g_kbias[M_TOK * NHEAD];
__device__ float g_bqkv[QKVS];
__device__ float g_entpart[1024];
__device__ __half g_src_f[M_TOK * D_MODEL];
__device__ __half g_qkv[M_TOK * QKVS];
__device__ __half g_at_f[M_TOK * D_MODEL];
__device__ __half g_x_f[M_TOK * D_MODEL];
__device__ __half g_ff_f[M_TOK * D_FF];
__device__ __half g_w4[4 * D_MODEL * D_MODEL];
__device__ __half g_w1[D_FF * D_MODEL];
__device__ __half g_w2[D_MODEL * D_FF];

// ======================= PTX helpers (baseline sm_103-legal only) ===========
__device__ __forceinline__ uint32_t smem_u32(const void* p) {
    uint32_t a;
    asm("{ .reg .u64 t; cvta.to.shared.u64 t, %1; cvt.u32.u64 %0, t; }" : "=r"(a) : "l"(p));
    return a;
}
__device__ __forceinline__ void cp16(uint32_t s, const void* g) {
    asm volatile("cp.async.cg.shared.global [%0], [%1], 16;" :: "r"(s), "l"(g));
}
__device__ __forceinline__ void cp4(uint32_t s, const void* g) {
    asm volatile("cp.async.ca.shared.global [%0], [%1], 4;" :: "r"(s), "l"(g));
}
#define CP_COMMIT() asm volatile("cp.async.commit_group;" ::: "memory")

__device__ __forceinline__ void ldsm4(uint32_t* r, uint32_t addr) {
    asm volatile("ldmatrix.sync.aligned.m8n8.x4.shared.b16 {%0,%1,%2,%3}, [%4];"
                 : "=r"(r[0]), "=r"(r[1]), "=r"(r[2]), "=r"(r[3]) : "r"(addr));
}
__device__ __forceinline__ void ldsm4t(uint32_t* r, uint32_t addr) {
    asm volatile("ldmatrix.sync.aligned.m8n8.x4.trans.shared.b16 {%0,%1,%2,%3}, [%4];"
                 : "=r"(r[0]), "=r"(r[1]), "=r"(r[2]), "=r"(r[3]) : "r"(addr));
}
__device__ __forceinline__ void mma16816(float* d, const uint32_t* a, uint32_t b0, uint32_t b1) {
    asm volatile(
        "mma.sync.aligned.m16n8k16.row.col.f32.f16.f16.f32 "
        "{%0,%1,%2,%3}, {%4,%5,%6,%7}, {%8,%9}, {%0,%1,%2,%3};"
        : "+f"(d[0]), "+f"(d[1]), "+f"(d[2]), "+f"(d[3])
        : "r"(a[0]), "r"(a[1]), "r"(a[2]), "r"(a[3]), "r"(b0), "r"(b1));
}
__device__ __forceinline__ uint32_t packh(float a, float b) {
    __half2 t = __floats2half2_rn(a, b);
    uint32_t u; memcpy(&u, &t, 4); return u;
}

// ======================= warp-MMA fp16 GEMM (BN=128, occ 2) =================
// BKC=64, SW128-swizzled 128B rows, 3 stages, ONE sync per chunk.
#define BM 128
#define BN 128
#define BKC 64
#define TILE_B (128 * 128)
#define STAGE_B (2 * TILE_B)
#define NSTAGE 3
#define GEMM_SMEM (NSTAGE * STAGE_B)

__device__ __forceinline__ void g_load_chunk(
    uint32_t smem, int ci, int m0, int n0, int K, int tid,
    const __half* __restrict__ A, const __half* __restrict__ W)
{
    uint32_t sb = smem + (uint32_t)(ci % NSTAGE) * STAGE_B;
    size_t kbase = (size_t)ci * BKC;
#pragma unroll
    for (int rep = 0; rep < 8; rep++) {
        int idx = tid + (rep << 8);
        int t = idx >> 10;
        int row = (idx >> 3) & 127;
        int seg = idx & 7;
        const __half* P = (t == 0) ? A : W;
        int r0 = (t == 0) ? m0 : n0;
        uint32_t sw = (uint32_t)((seg << 4) ^ ((row & 7) << 4));
        cp16(sb + (uint32_t)t * TILE_B + (uint32_t)(row << 7) + sw,
             P + (size_t)(r0 + row) * K + kbase + seg * 8);
    }
}

template <int MODE>
__global__ void __launch_bounds__(256, 2) tcgemm_kernel(
    const __half* __restrict__ A, const __half* __restrict__ W,
    const float* __restrict__ bias, const float* __restrict__ res,
    float* __restrict__ C, __half* __restrict__ Cf,
    int M, int N, int K)
{
    extern __shared__ char dsm[];
    uint32_t smem = smem_u32(dsm);

    int tid = threadIdx.x;
    int wid = tid >> 5;
    int lane = tid & 31;
    int m0 = blockIdx.y * BM;
    int n0 = blockIdx.x * BN;
    int nchunk = K / BKC;

    int wm = wid & 1;
    int wn = wid >> 1;
    int lr = lane & 15;
    uint32_t lk = (uint32_t)((lane >> 4) << 4);
    uint32_t swz = (uint32_t)((lr & 7) << 4);

    float acc[4][4][4];
#pragma unroll
    for (int i = 0; i < 4; i++)
#pragma unroll
        for (int j = 0; j < 4; j++)
#pragma unroll
            for (int c = 0; c < 4; c++) acc[i][j][c] = 0.0f;

    g_load_chunk(smem, 0, m0, n0, K, tid, A, W);
    CP_COMMIT();
    g_load_chunk(smem, 1, m0, n0, K, tid, A, W);
    CP_COMMIT();

    for (int i = 0; i < nchunk; i++) {
        if (i < nchunk - 1)
            asm volatile("cp.async.wait_group 1;" ::: "memory");
        else
            asm volatile("cp.async.wait_group 0;" ::: "memory");
        __syncthreads();

        if (i + 2 < nchunk) {
            g_load_chunk(smem, i + 2, m0, n0, K, tid, A, W);
            CP_COMMIT();
        }

        uint32_t sb = smem + (uint32_t)(i % NSTAGE) * STAGE_B;
        uint32_t aRow = sb + (uint32_t)((wm * 64 + lr) << 7);
        uint32_t bRow = sb + TILE_B + (uint32_t)((wn * 32 + lr) << 7);

#pragma unroll
        for (int ks = 0; ks < 4; ks++) {
            uint32_t col = ((uint32_t)(ks * 32) + lk) ^ swz;
            uint32_t ah[4][4];
#pragma unroll
            for (int mt = 0; mt < 4; mt++)
                ldsm4(ah[mt], aRow + (uint32_t)(mt << 11) + col);
#pragma unroll
            for (int nt = 0; nt < 2; nt++) {
                uint32_t bb[4];
                ldsm4(bb, bRow + (uint32_t)(nt << 11) + col);
#pragma unroll
                for (int mt = 0; mt < 4; mt++) {
                    mma16816(acc[mt][nt * 2],     ah[mt], bb[0], bb[2]);
                    mma16816(acc[mt][nt * 2 + 1], ah[mt], bb[1], bb[3]);
                }
            }
        }
    }

    int rbase = m0 + wm * 64 + (lane >> 2);
    int cbase = n0 + wn * 32 + (lane & 3) * 2;
#pragma unroll
    for (int mt = 0; mt < 4; mt++) {
#pragma unroll
        for (int n8 = 0; n8 < 4; n8++) {
            int col = cbase + n8 * 8;
            float b0 = bias[col], b1 = bias[col + 1];
#pragma unroll
            for (int half = 0; half < 2; half++) {
                int row = rbase + mt * 16 + half * 8;
                float v0 = acc[mt][n8][half * 2] + b0;
                float v1 = acc[mt][n8][half * 2 + 1] + b1;
                if (MODE == 1) {
                    v0 = 0.5f * v0 * (1.0f + erff(v0 * 0.70710678118654752f));
                    v1 = 0.5f * v1 * (1.0f + erff(v1 * 0.70710678118654752f));
                }
                if (MODE == 2) {
                    const float2 rv = *(const float2*)(res + (size_t)row * N + col);
                    v0 += rv.x; v1 += rv.y;
                }
                if (MODE == 0 || MODE == 2) {
                    float2 o; o.x = v0; o.y = v1;
                    *(float2*)(C + (size_t)row * N + col) = o;
                } else {
                    *(__half2*)(Cf + (size_t)row * N + col) = __floats2half2_rn(v0, v1);
                }
            }
        }
    }
}

// ======================= warp-MMA fp16 GEMM (BN=64, occ 3) ==================
// Measured faster for the QKV shape (M=4096,N=3072,K=1024): 88.0 -> 84.7us.
#define T64_A (128 * 128)                // 16384
#define T64_W (64 * 128)                 // 8192
#define STAGE64 (T64_A + T64_W)          // 24576
#define GEMM64_SMEM (3 * STAGE64)        // 73728 -> 3 CTAs/SM

__device__ __forceinline__ void g_load_chunk64(
    uint32_t smem, int ci, int m0, int n0, int K, int tid,
    const __half* __restrict__ A, const __half* __restrict__ W)
{
    uint32_t sb = smem + (uint32_t)(ci % 3) * STAGE64;
    size_t kbase = (size_t)ci * BKC;
#pragma unroll
    for (int rep = 0; rep < 6; rep++) {
        int idx = tid + (rep << 8);          // 0..1535
        int isB = idx >> 10;                 // 0 = A (1024), 1 = W (512)
        int row = (idx >> 3) & (isB ? 63 : 127);
        int seg = idx & 7;
        const __half* P = isB ? W : A;
        int r0 = isB ? n0 : m0;
        uint32_t off = isB ? (uint32_t)T64_A : 0u;
        uint32_t sw = (uint32_t)((seg << 4) ^ ((row & 7) << 4));
        cp16(sb + off + (uint32_t)(row << 7) + sw,
             P + (size_t)(r0 + row) * K + kbase + seg * 8);
    }
}

__global__ void __launch_bounds__(256, 3) tcgemm64_kernel(
    const __half* __restrict__ A, const __half* __restrict__ W,
    const float* __restrict__ bias, __half* __restrict__ Cf,
    int M, int N, int K)
{
    extern __shared__ char dsm[];
    uint32_t smem = smem_u32(dsm);

    int tid = threadIdx.x;
    int wid = tid >> 5;
    int lane = tid & 31;
    int m0 = blockIdx.y * BM;
    int n0 = blockIdx.x * 64;
    int nchunk = K / BKC;

    int wm = wid & 3;
    int wn = wid >> 2;
    int lr = lane & 15;
    uint32_t lk = (uint32_t)((lane >> 4) << 4);
    uint32_t swz = (uint32_t)((lr & 7) << 4);

    float acc[2][4][4];
#pragma unroll
    for (int i = 0; i < 2; i++)
#pragma unroll
        for (int j = 0; j < 4; j++)
#pragma unroll
            for (int c = 0; c < 4; c++) acc[i][j][c] = 0.0f;

    g_load_chunk64(smem, 0, m0, n0, K, tid, A, W);
    CP_COMMIT();
    g_load_chunk64(smem, 1, m0, n0, K, tid, A, W);
    CP_COMMIT();

    for (int i = 0; i < nchunk; i++) {
        if (i < nchunk - 1)
            asm volatile("cp.async.wait_group 1;" ::: "memory");
        else
            asm volatile("cp.async.wait_group 0;" ::: "memory");
        __syncthreads();

        if (i + 2 < nchunk) {
            g_load_chunk64(smem, i + 2, m0, n0, K, tid, A, W);
            CP_COMMIT();
        }

        uint32_t sb = smem + (uint32_t)(i % 3) * STAGE64;
        uint32_t aRow = sb + (uint32_t)((wm * 32 + lr) << 7);
        uint32_t bRow = sb + T64_A + (uint32_t)((wn * 32 + lr) << 7);

#pragma unroll
        for (int ks = 0; ks < 4; ks++) {
            uint32_t col = ((uint32_t)(ks * 32) + lk) ^ swz;
            uint32_t ah[2][4], bb[2][4];
            ldsm4(ah[0], aRow + col);
            ldsm4(ah[1], aRow + (1u << 11) + col);
            ldsm4(bb[0], bRow + col);
            ldsm4(bb[1], bRow + (1u << 11) + col);
#pragma unroll
            for (int nt = 0; nt < 2; nt++)
#pragma unroll
                for (int mt = 0; mt < 2; mt++) {
                    mma16816(acc[mt][nt * 2],     ah[mt], bb[nt][0], bb[nt][2]);
                    mma16816(acc[mt][nt * 2 + 1], ah[mt], bb[nt][1], bb[nt][3]);
                }
        }
    }

    int rbase = m0 + wm * 32 + (lane >> 2);
    int cbase = n0 + wn * 32 + (lane & 3) * 2;
#pragma unroll
    for (int mt = 0; mt < 2; mt++) {
#pragma unroll
        for (int n8 = 0; n8 < 4; n8++) {
            int col = cbase + n8 * 8;
            float b0 = bias[col], b1 = bias[col + 1];
#pragma unroll
            for (int half = 0; half < 2; half++) {
                int row = rbase + mt * 16 + half * 8;
                float v0 = acc[mt][n8][half * 2] + b0;
                float v1 = acc[mt][n8][half * 2 + 1] + b1;
                *(__half2*)(Cf + (size_t)row * N + col) = __floats2half2_rn(v0, v1);
            }
        }
    }
}

// ======================= MMA flash attention ================================
#define ASTR 144
#define ATILE (64 * ASTR)
#define ASTAGE (2 * ATILE + 256)
#define ANST 3
#define ASMEM (ANST * ASTAGE + 64)

__device__ __forceinline__ void a_load_chunk(
    uint32_t sm0, int ci, size_t tokb, int h, int tid,
    const __half* __restrict__ QKV, const float* __restrict__ kb)
{
    uint32_t st = sm0 + (uint32_t)(ci % ANST) * ASTAGE;
    size_t rowb = tokb + (size_t)ci * 64;
#pragma unroll
    for (int r = 0; r < 4; r++) {
        int idx = tid + (r << 8);
        int t = idx >> 9;
        int row = (idx >> 3) & 63;
        int seg = idx & 7;
        cp16(st + (uint32_t)t * ATILE + (uint32_t)row * ASTR + (uint32_t)seg * 16,
             QKV + (rowb + row) * QKVS + (t + 1) * D_MODEL + h * HEAD_DIM + seg * 8);
    }
    if (tid < 64)
        cp4(st + 2u * ATILE + (uint32_t)tid * 4, kb + (rowb + tid) * NHEAD + h);
}

__global__ void __launch_bounds__(256, 2) attn_mma_kernel(
    const __half* __restrict__ QKV,
    const float* __restrict__ qb, const float* __restrict__ kb,
    const float* __restrict__ temp,
    __half* __restrict__ Of, float* __restrict__ ent_part)
{
    extern __shared__ char smemv[];
    uint32_t sm0 = smem_u32(smemv);
    float* red = (float*)(smemv + ANST * ASTAGE);

    int tid = threadIdx.x;
    int w = tid >> 5;
    int lane = tid & 31;
    int q0 = blockIdx.x * 128;
    int h = blockIdx.y;
    int b = blockIdx.z;
    size_t tokb = (size_t)b * L_;

    float tmph = fminf(fmaxf(temp[h], 0.1f), 5.0f);
    float inv_t = 1.0f / tmph;
    float sc = 0.125f * inv_t;

    uint32_t qarea = sm0 + 2u * ASTAGE;
    for (int i = tid; i < 128 * 8; i += 256) {
        int row = i >> 3, seg = i & 7;
        cp16(qarea + (uint32_t)row * ASTR + (uint32_t)seg * 16,
             QKV + (tokb + q0 + row) * QKVS + h * HEAD_DIM + seg * 8);
    }
    CP_COMMIT();
    a_load_chunk(sm0, 0, tokb, h, tid, QKV, kb);
    CP_COMMIT();
    a_load_chunk(sm0, 1, tokb, h, tid, QKV, kb);
    CP_COMMIT();

    asm volatile("cp.async.wait_group 2;" ::: "memory");
    __syncthreads();

    uint32_t qfr[4][4];
    {
        uint32_t qbase = qarea + (uint32_t)(w * 16 + (lane & 15)) * ASTR + (uint32_t)((lane >> 4) << 4);
#pragma unroll
        for (int ks = 0; ks < 4; ks++) ldsm4(qfr[ks], qbase + ks * 32);
    }
    int gid = lane >> 2, tig = lane & 3;
    int r0 = q0 + w * 16 + gid, r1 = r0 + 8;
    float qb0 = qb[(tokb + r0) * NHEAD + h] * inv_t;
    float qb1 = qb[(tokb + r1) * NHEAD + h] * inv_t;

    float O[8][4];
#pragma unroll
    for (int f = 0; f < 8; f++)
#pragma unroll
        for (int c = 0; c < 4; c++) O[f][c] = 0.0f;
    float m0 = -1e30f, m1 = -1e30f, z0 = 0.0f, z1 = 0.0f, t0 = 0.0f, t1 = 0.0f;

    const int NCH = L_ / 64;
    for (int ci = 0; ci < NCH; ci++) {
        if (ci < NCH - 1)
            asm volatile("cp.async.wait_group 1;" ::: "memory");
        else
            asm volatile("cp.async.wait_group 0;" ::: "memory");
        __syncthreads();

        if (ci + 2 < NCH) {
            a_load_chunk(sm0, ci + 2, tokb, h, tid, QKV, kb);
            CP_COMMIT();
        }

        uint32_t st = sm0 + (uint32_t)(ci % ANST) * ASTAGE;
        uint32_t kbh = st + (uint32_t)(lane & 15) * ASTR + (uint32_t)((lane >> 4) << 4);

        float S[8][4];
#pragma unroll
        for (int f = 0; f < 8; f++)
#pragma unroll
            for (int c = 0; c < 4; c++) S[f][c] = 0.0f;

#pragma unroll
        for (int ks = 0; ks < 4; ks++) {
            uint32_t koff = (uint32_t)ks * 32;
#pragma unroll
            for (int nt = 0; nt < 4; nt++) {
                uint32_t bb[4];
                ldsm4(bb, kbh + (uint32_t)(nt * 16) * ASTR + koff);
                mma16816(S[nt * 2],     qfr[ks], bb[0], bb[2]);
                mma16816(S[nt * 2 + 1], qfr[ks], bb[1], bb[3]);
            }
        }

        const float* kbs = (const float*)(smemv + (size_t)((ci % ANST) * ASTAGE + 2 * ATILE));
        float mx0 = -1e30f, mx1 = -1e30f;
#pragma unroll
        for (int f = 0; f < 8; f++) {
            float kc0 = kbs[f * 8 + 2 * tig] * inv_t;
            float kc1 = kbs[f * 8 + 2 * tig + 1] * inv_t;
            S[f][0] = S[f][0] * sc + qb0 + kc0;
            S[f][1] = S[f][1] * sc + qb0 + kc1;
            S[f][2] = S[f][2] * sc + qb1 + kc0;
            S[f][3] = S[f][3] * sc + qb1 + kc1;
            mx0 = fmaxf(mx0, fmaxf(S[f][0], S[f][1]));
            mx1 = fmaxf(mx1, fmaxf(S[f][2], S[f][3]));
        }
        mx0 = fmaxf(mx0, __shfl_xor_sync(0xffffffffu, mx0, 1));
        mx0 = fmaxf(mx0, __shfl_xor_sync(0xffffffffu, mx0, 2));
        mx1 = fmaxf(mx1, __shfl_xor_sync(0xffffffffu, mx1, 1));
        mx1 = fmaxf(mx1, __shfl_xor_sync(0xffffffffu, mx1, 2));

        float nm0 = fmaxf(m0, mx0), nm1 = fmaxf(m1, mx1);
        float sc0 = __expf(m0 - nm0), sc1 = __expf(m1 - nm1);
        float zc0 = 0.0f, zc1 = 0.0f, tc0 = 0.0f, tc1 = 0.0f;
        uint32_t pa[4][4];
#pragma unroll
        for (int j = 0; j < 4; j++) {
#pragma unroll
            for (int g = 0; g < 2; g++) {
                int f = 2 * j + g;
                float p0 = __expf(S[f][0] - nm0);
                float p1 = __expf(S[f][1] - nm0);
                float p2 = __expf(S[f][2] - nm1);
                float p3 = __expf(S[f][3] - nm1);
                zc0 += p0 + p1; zc1 += p2 + p3;
                tc0 += p0 * S[f][0] + p1 * S[f][1];
                tc1 += p2 * S[f][2] + p3 * S[f][3];
                pa[j][g * 2]     = packh(p0, p1);
                pa[j][g * 2 + 1] = packh(p2, p3);
            }
        }
        zc0 += __shfl_xor_sync(0xffffffffu, zc0, 1); zc0 += __shfl_xor_sync(0xffffffffu, zc0, 2);
        zc1 += __shfl_xor_sync(0xffffffffu, zc1, 1); zc1 += __shfl_xor_sync(0xffffffffu, zc1, 2);
        tc0 += __shfl_xor_sync(0xffffffffu, tc0, 1); tc0 += __shfl_xor_sync(0xffffffffu, tc0, 2);
        tc1 += __shfl_xor_sync(0xffffffffu, tc1, 1); tc1 += __shfl_xor_sync(0xffffffffu, tc1, 2);
        z0 = z0 * sc0 + zc0; t0 = t0 * sc0 + tc0; m0 = nm0;
        z1 = z1 * sc1 + zc1; t1 = t1 * sc1 + tc1; m1 = nm1;
#pragma unroll
        for (int f = 0; f < 8; f++) {
            O[f][0] *= sc0; O[f][1] *= sc0; O[f][2] *= sc1; O[f][3] *= sc1;
        }

        uint32_t vb = st + ATILE + (uint32_t)(lane & 15) * ASTR + (uint32_t)((lane >> 4) << 4);
#pragma unroll
        for (int j = 0; j < 4; j++) {
            uint32_t vrow = vb + (uint32_t)(j * 16) * ASTR;
#pragma unroll
            for (int hg = 0; hg < 4; hg++) {
                uint32_t v[4];
                ldsm4t(v, vrow + (uint32_t)hg * 32);
                mma16816(O[hg * 2],     pa[j], v[0], v[1]);
                mma16816(O[hg * 2 + 1], pa[j], v[2], v[3]);
            }
        }
    }

    float iz0 = 1.0f / z0, iz1 = 1.0f / z1;
    size_t row0b = (tokb + r0) * D_MODEL, row1b = (tokb + r1) * D_MODEL;
#pragma unroll
    for (int f = 0; f < 8; f++) {
        int col = h * HEAD_DIM + f * 8 + 2 * tig;
        *(__half2*)(Of + row0b + col) = __floats2half2_rn(O[f][0] * iz0, O[f][1] * iz0);
        *(__half2*)(Of + row1b + col) = __floats2half2_rn(O[f][2] * iz1, O[f][3] * iz1);
    }

    float Hv = (m0 + logf(z0) - t0 / z0 + m1 + logf(z1) - t1 / z1) * 0.25f;
#pragma unroll
    for (int off = 16; off; off >>= 1) Hv += __shfl_xor_sync(0xffffffffu, Hv, off);
    if (lane == 0) red[w] = Hv;
    __syncthreads();
    if (tid == 0) {
        float s = 0.0f;
#pragma unroll
        for (int i = 0; i < 8; i++) s += red[i];
        ent_part[((b * NHEAD + h) << 4) + blockIdx.x] = s;
    }
}

// ======================= all weight transposes in ONE launch ================
__global__ void __launch_bounds__(256) convAll_kernel(
    const float* __restrict__ Wq, const float* __restrict__ Wk,
    const float* __restrict__ Wv, const float* __restrict__ Wo,
    const float* __restrict__ W1, const float* __restrict__ W2,
    __half* __restrict__ w4, __half* __restrict__ w1o, __half* __restrict__ w2o)
{
    __shared__ float t[32][33];
    int id = blockIdx.x;
    const float* W; __half* dst; int K, N, n0, k0;
    if (id < 4096) {
        int slab = id >> 10, tt = id & 1023;
        W = (slab == 0) ? Wq : (slab == 1) ? Wk : (slab == 2) ? Wv : Wo;
        dst = w4 + (size_t)slab * D_MODEL * D_MODEL;
        K = D_MODEL; N = D_MODEL;
        n0 = (tt & 31) << 5; k0 = (tt >> 5) << 5;
    } else if (id < 8192) {
        int tt = id - 4096;
        W = W1; dst = w1o; K = D_MODEL; N = D_FF;
        n0 = (tt & 127) << 5; k0 = (tt >> 7) << 5;
    } else {
        int tt = id - 8192;
        W = W2; dst = w2o; K = D_FF; N = D_MODEL;
        n0 = (tt & 31) << 5; k0 = (tt >> 5) << 5;
    }
    int tx = threadIdx.x & 31, ty = threadIdx.x >> 5;
#pragma unroll
    for (int i = 0; i < 32; i += 8)
        t[ty + i][tx] = W[(size_t)(k0 + ty + i) * N + n0 + tx];
    __syncthreads();
#pragma unroll
    for (int i = 0; i < 32; i += 8)
        dst[(size_t)(n0 + ty + i) * K + k0 + tx] = __float2half_rn(t[tx][ty + i]);
}

__global__ void __launch_bounds__(256) conv_kernel(
    const float* __restrict__ in, __half* __restrict__ outp, int n4,
    const float* __restrict__ bq, const float* __restrict__ bk,
    const float* __restrict__ bv, float* __restrict__ bqkv)
{
    if (blockIdx.x == gridDim.x - 1) {
        int tid = threadIdx.x;
        for (int i = tid; i < D_MODEL; i += 256) {
            bqkv[i] = bq[i];
            bqkv[i + D_MODEL] = bk[i];
            bqkv[i + 2 * D_MODEL] = bv[i];
        }
        return;
    }
    int i = blockIdx.x * 256 + threadIdx.x;
    if (i >= n4) return;
    float4 v = ((const float4*)in)[i];
    ((__half2*)outp)[i * 2]     = __floats2half2_rn(v.x, v.y);
    ((__half2*)outp)[i * 2 + 1] = __floats2half2_rn(v.z, v.w);
}

// ---------------- POS bias MLPs ----------------------------------------------
__global__ void __launch_bounds__(128) posbias_kernel(
    const float* __restrict__ pos,
    const float* __restrict__ qw1, const float* __restrict__ qb1,
    const float* __restrict__ qw2, const float* __restrict__ qb2,
    const float* __restrict__ kw1, const float* __restrict__ kb1,
    const float* __restrict__ kw2, const float* __restrict__ kb2,
    float* __restrict__ qbias, float* __restrict__ kbias)
{
    __shared__ float sw1q[32 * 32], sw2q[32 * 16], sb1q[32], sb2q[16];
    __shared__ float sw1k[32 * 32], sw2k[32 * 16], sb1k[32], sb2k[16];
    int tid = threadIdx.x;
    for (int i = tid; i < 1024; i += 128) { sw1q[i] = qw1[i]; sw1k[i] = kw1[i]; }
    for (int i = tid; i < 512;  i += 128) { sw2q[i] = qw2[i]; sw2k[i] = kw2[i]; }
    if (tid < 32) { sb1q[tid] = qb1[tid]; sb1k[tid] = kb1[tid]; }
    if (tid < 16) { sb2q[tid] = qb2[tid]; sb2k[tid] = kb2[tid]; }
    __syncthreads();

    int token = blockIdx.x * 128 + tid;
    float pf[32];
#pragma unroll
    for (int i = 0; i < 32; i++) pf[i] = pos[(size_t)token * 32 + i];

    float hq[32], hk[32];
#pragma unroll
    for (int j = 0; j < 32; j++) { hq[j] = sb1q[j]; hk[j] = sb1k[j]; }
    for (int i = 0; i < 32; i++) {
        float p = pf[i];
#pragma unroll
        for (int j = 0; j < 32; j++) {
            hq[j] += p * sw1q[i * 32 + j];
            hk[j] += p * sw1k[i * 32 + j];
        }
    }
#pragma unroll
    for (int j = 0; j < 32; j++) {
        hq[j] = fmaxf(hq[j], 0.0f);
        hk[j] = fmaxf(hk[j], 0.0f);
    }
#pragma unroll
    for (int h = 0; h < 16; h++) {
        float oq = sb2q[h], ok = sb2k[h];
        for (int j = 0; j < 32; j++) {
            oq += hq[j] * sw2q[j * 16 + h];
            ok += hk[j] * sw2k[j * 16 + h];
        }
        qbias[(size_t)token * NHEAD + h] = oq;
        kbias[(size_t)token * NHEAD + h] = ok;
    }
}

// ---------------- layernorm (optionally emits fp16) --------------------------
template <int SPLIT>
__global__ void __launch_bounds__(256) ln_kernel(
    const float* __restrict__ in, const float* __restrict__ gam,
    const float* __restrict__ bet, float* __restrict__ out,
    __half* __restrict__ of)
{
    int row = blockIdx.x, tid = threadIdx.x;
    float4 v = ((const float4*)(in + (size_t)row * D_MODEL))[tid];
    float s = v.x + v.y + v.z + v.w;
    float q = v.x * v.x + v.y * v.y + v.z * v.z + v.w * v.w;
#pragma unroll
    for (int off = 16; off; off >>= 1) {
        s += __shfl_xor_sync(0xffffffffu, s, off);
        q += __shfl_xor_sync(0xffffffffu, q, off);
    }
    __shared__ float ws[8], wq[8], stats[2];
    int lane = tid & 31, w = tid >> 5;
    if (lane == 0) { ws[w] = s; wq[w] = q; }
    __syncthreads();
    if (tid == 0) {
        float S = 0.0f, Qq = 0.0f;
        for (int i = 0; i < 8; i++) { S += ws[i]; Qq += wq[i]; }
        float mu  = S * (1.0f / D_MODEL);
        float var = Qq * (1.0f / D_MODEL) - mu * mu;
        stats[0] = mu;
        stats[1] = rsqrtf(var + 1e-5f);
    }
    __syncthreads();
    float mu = stats[0], rs = stats[1];
    float4 gv = ((const float4*)gam)[tid];
    float4 bv = ((const float4*)bet)[tid];
    float4 ov;
    ov.x = (v.x - mu) * rs * gv.x + bv.x;
    ov.y = (v.y - mu) * rs * gv.y + bv.y;
    ov.z = (v.z - mu) * rs * gv.z + bv.z;
    ov.w = (v.w - mu) * rs * gv.w + bv.w;
    ((float4*)(out + (size_t)row * D_MODEL))[tid] = ov;
    if (SPLIT) {
        size_t base = (size_t)row * D_MODEL + tid * 4;
        *(__half2*)(of + base)     = __floats2half2_rn(ov.x, ov.y);
        *(__half2*)(of + base + 2) = __floats2half2_rn(ov.z, ov.w);
    }
}

// ---------------- deterministic entropy reduction ----------------------------
__global__ void __launch_bounds__(256) ent_final_kernel(
    const float* __restrict__ part, float* __restrict__ out, int out_size)
{
    __shared__ float sm[256];
    int tid = threadIdx.x;
    sm[tid] = part[tid] + part[tid + 256];
    __syncthreads();
    for (int off = 128; off; off >>= 1) {
        if (tid < off) sm[tid] += sm[tid + off];
        __syncthreads();
    }
    if (tid == 0 && out_size > OUT_MAIN)
        out[OUT_MAIN] = sm[0] * (1.0f / (B_ * NHEAD * L_));
}

// ---------------- launch -----------------------------------------------------
extern "C" void kernel_launch(void* const* d_in, const int* in_sizes, int n_in,
                              void* d_out, int out_size)
{
    const float* src   = (const float*)d_in[0];
    const float* pos   = (const float*)d_in[1];
    const float* Wq    = (const float*)d_in[2];
    const float* bq    = (const float*)d_in[3];
    const float* Wk    = (const float*)d_in[4];
    const float* bk    = (const float*)d_in[5];
    const float* Wv    = (const float*)d_in[6];
    const float* bv    = (const float*)d_in[7];
    const float* Wo    = (const float*)d_in[8];
    const float* bo    = (const float*)d_in[9];
    const float* pq_w1 = (const float*)d_in[10];
    const float* pq_b1 = (const float*)d_in[11];
    const float* pq_w2 = (const float*)d_in[12];
    const float* pq_b2 = (const float*)d_in[13];
    const float* pk_w1 = (const float*)d_in[14];
    const float* pk_b1 = (const float*)d_in[15];
    const float* pk_w2 = (const float*)d_in[16];
    const float* pk_b2 = (const float*)d_in[17];
    const float* temp  = (const float*)d_in[18];
    const float* ln1g  = (const float*)d_in[19];
    const float* ln1b  = (const float*)d_in[20];
    const float* ln2g  = (const float*)d_in[21];
    const float* ln2b  = (const float*)d_in[22];
    const float* W1    = (const float*)d_in[23];
    const float* b1    = (const float*)d_in[24];
    const float* W2    = (const float*)d_in[25];
    const float* b2    = (const float*)d_in[26];
    float* out = (float*)d_out;

    float *xb, *yb, *qbb, *kbb, *entp, *bqkv;
    cudaGetSymbolAddress((void**)&xb, g_x);
    cudaGetSymbolAddress((void**)&yb, g_y);
    cudaGetSymbolAddress((void**)&qbb, g_qbias);
    cudaGetSymbolAddress((void**)&kbb, g_kbias);
    cudaGetSymbolAddress((void**)&entp, g_entpart);
    cudaGetSymbolAddress((void**)&bqkv, g_bqkv);

    __half *srcf, *qkv, *atf, *xf, *fff;
    __half *w4, *w116, *w216;
    cudaGetSymbolAddress((void**)&srcf, g_src_f);
    cudaGetSymbolAddress((void**)&qkv, g_qkv);
    cudaGetSymbolAddress((void**)&atf, g_at_f);
    cudaGetSymbolAddress((void**)&xf, g_x_f);
    cudaGetSymbolAddress((void**)&fff, g_ff_f);
    cudaGetSymbolAddress((void**)&w4, g_w4);
    cudaGetSymbolAddress((void**)&w116, g_w1);
    cudaGetSymbolAddress((void**)&w216, g_w2);

    __half* wo16 = w4 + 3 * (size_t)D_MODEL * D_MODEL;

    cudaFuncSetAttribute(tcgemm_kernel<1>, cudaFuncAttributeMaxDynamicSharedMemorySize, GEMM_SMEM);
    cudaFuncSetAttribute(tcgemm_kernel<2>, cudaFuncAttributeMaxDynamicSharedMemorySize, GEMM_SMEM);
    cudaFuncSetAttribute(tcgemm64_kernel, cudaFuncAttributeMaxDynamicSharedMemorySize, GEMM64_SMEM);
    cudaFuncSetAttribute(attn_mma_kernel, cudaFuncAttributeMaxDynamicSharedMemorySize, ASMEM);

    convAll_kernel<<<12288, 256>>>(Wq, Wk, Wv, Wo, W1, W2, w4, w116, w216);
    conv_kernel<<<M_TOK * D_MODEL / 4 / 256 + 1, 256>>>(src, srcf, M_TOK * D_MODEL / 4,
                                                        bq, bk, bv, bqkv);
    posbias_kernel<<<M_TOK / 128, 128>>>(pos, pq_w1, pq_b1, pq_w2, pq_b2,
                                         pk_w1, pk_b1, pk_w2, pk_b2, qbb, kbb);

    // fused QKV projection (BN=64/occ-3 variant: measured faster on this shape)
    dim3 gQKV(QKVS / 64, M_TOK / BM);   // (48, 32)
    tcgemm64_kernel<<<gQKV, 256, GEMM64_SMEM>>>(srcf, w4, bqkv, qkv,
                                                M_TOK, QKVS, D_MODEL);

    attn_mma_kernel<<<dim3(L_ / 128, NHEAD, B_), 256, ASMEM>>>(
        qkv, qbb, kbb, temp, atf, entp);

    dim3 gD(D_MODEL / BN, M_TOK / BM);  // (8, 32)
    tcgemm_kernel<2><<<gD, 256, GEMM_SMEM>>>(atf, wo16, bo, src,
                                             yb, (__half*)0, M_TOK, D_MODEL, D_MODEL);
    ln_kernel<1><<<M_TOK, 256>>>(yb, ln1g, ln1b, xb, xf);

    dim3 gF(D_FF / BN, M_TOK / BM);     // (32, 32)
    tcgemm_kernel<1><<<gF, 256, GEMM_SMEM>>>(xf, w116, b1, (const float*)0,
                                             (float*)0, fff, M_TOK, D_FF, D_MODEL);
    tcgemm_kernel<2><<<gD, 256, GEMM_SMEM>>>(fff, w216, b2, xb,
                                             yb, (__half*)0, M_TOK, D_MODEL, D_FF);
    ln_kernel<0><<<M_TOK, 256>>>(yb, ln2g, ln2b, out, (__half*)0);

    ent_final_kernel<<<1, 256>>>(entp, out, out_size);
}